// round 15
// baseline (speedup 1.0000x reference)
#include <cuda_runtime.h>
#include <cstdint>

#define M 8192
#define NW 128          // 64-bit words per row (M/64)
#define NMS_T 0.3f
#define CH 256          // scan chunk size (elements)
#define WPC 4           // words per chunk (CH/64)
#define TILE 2048       // sort tile size
#define NTILE 4         // number of sort tiles (M/TILE)

typedef unsigned long long u64;

// ---------------- device scratch (no runtime allocation allowed) ------------
__device__ float  g_d[M * 5];        // transformed detections (orig order)
__device__ u64    g_ckey[M];         // packed (key<<13 | idx), padded to 8192
__device__ int    g_cnt;             // valid count (atomic; reset by scan)
__device__ int    g_V;               // valid count (published by lsort)
__device__ float  g_ds[M * 5];       // sorted detections (first V rows)
__device__ float4 g_boxes[M];        // x1,y1,x2,y2 (sorted order, first V)
__device__ u64    g_mask[M * NW];    // suppression bitmask (i>j bits only)

// ---------------- kernel 1: transform + score + compact (coalesced) ---------
__global__ void __launch_bounds__(256)
prep_kernel(const float* __restrict__ det, const float* __restrict__ off,
            const float* __restrict__ scl, const float* __restrict__ bnd) {
    __shared__ float srow[256 * 5];
    int b = blockIdx.x;                    // 32 blocks x 256 rows
    int tid = threadIdx.x;
    int lane = tid & 31;
    const float* src = det + b * 256 * 5;
    for (int i = tid; i < 256 * 5; i += 256) srow[i] = src[i];
    __syncthreads();

    int i = b * 256 + tid;                 // global row
    int w = i >> 10;
    float a0 = srow[tid * 5 + 0], a1 = srow[tid * 5 + 1], a2 = srow[tid * 5 + 2];
    float a3 = srow[tid * 5 + 3], a4 = srow[tid * 5 + 4];
    float d0 = off[w * 5 + 0] + a0 * scl[w * 5 + 0];
    float d1 = off[w * 5 + 1] + a1 * scl[w * 5 + 1];
    float d2 = off[w * 5 + 2] + a2 * scl[w * 5 + 2];
    float d3 = off[w * 5 + 3] + a3 * scl[w * 5 + 3];
    float d4 = off[w * 5 + 4] + a4 * scl[w * 5 + 4];
    bool valid = (a1 < bnd[w * 4 + 1]) && (a1 > bnd[w * 4 + 0]) &&
                 (a2 < bnd[w * 4 + 3]) && (a2 > bnd[w * 4 + 2]);

    g_d[i * 5 + 0] = d0;
    g_d[i * 5 + 1] = d1;
    g_d[i * 5 + 2] = d2;
    g_d[i * 5 + 3] = d3;
    g_d[i * 5 + 4] = d4;

    bool take = valid && d0 > 0.0f;        // non-positive scores -> zero rows
    unsigned ball = __ballot_sync(0xffffffffu, take);
    if (ball) {
        int nb = __popc(ball);
        int leader = __ffs(ball) - 1;
        int base = 0;
        if (lane == leader) base = atomicAdd(&g_cnt, nb);
        base = __shfl_sync(0xffffffffu, base, leader);
        if (take) {
            int o = __popc(ball & ((1u << lane) - 1));
            unsigned key = ~(__float_as_uint(d0) | 0x80000000u);
            g_ckey[base + o] = ((u64)key << 13) | (u64)i;  // (score desc, idx asc)
        }
    }
}

// ---------------- kernel 2a: local bitonic sort of 2048-tiles ---------------
__global__ void __launch_bounds__(1024) lsort_kernel() {
    __shared__ u64 sv[TILE];
    int tb = blockIdx.x << 11;
    int tid = threadIdx.x;
    int V = g_cnt;
    if (tb == 0 && tid == 0) g_V = V;

    if (tb >= V) {                         // pure padding tile: just materialize
        g_ckey[tb + tid] = ~0ull;
        g_ckey[tb + tid + 1024] = ~0ull;
        return;
    }

    u64 r0 = (tb + tid < V) ? g_ckey[tb + tid] : ~0ull;
    u64 r1 = (tb + tid + 1024 < V) ? g_ckey[tb + tid + 1024] : ~0ull;

    // phase A: k = 2..32 entirely in registers (intra-warp shuffles)
    int e0 = tb + tid, e1 = tb + 1024 + tid;
#pragma unroll
    for (int k = 2; k <= 32; k <<= 1) {
#pragma unroll
        for (int s = k >> 1; s >= 1; s >>= 1) {
            u64 o0 = __shfl_xor_sync(0xffffffffu, r0, s);
            u64 o1 = __shfl_xor_sync(0xffffffffu, r1, s);
            bool m0 = (((e0 & s) == 0) == ((e0 & k) == 0));
            bool m1 = (((e1 & s) == 0) == ((e1 & k) == 0));
            r0 = ((r0 < o0) == m0) ? r0 : o0;
            r1 = ((r1 < o1) == m1) ? r1 : o1;
        }
    }
    sv[tid] = r0;
    sv[tid + 1024] = r1;
    __syncthreads();

    // phase B: k = 64..2048 (strides >=32 in smem, <=16 via shuffles)
#pragma unroll
    for (int k = 64; k <= TILE; k <<= 1) {
        for (int s = k >> 1; s >= 32; s >>= 1) {
            int a = ((tid & ~(s - 1)) << 1) | (tid & (s - 1));
            bool up = (((tb + a) & k) == 0);
            u64 x = sv[a], y = sv[a + s];
            if ((x > y) == up) { sv[a] = y; sv[a + s] = x; }
            __syncthreads();
        }
        r0 = sv[tid];
        r1 = sv[tid + 1024];
#pragma unroll
        for (int s = 16; s >= 1; s >>= 1) {
            u64 o0 = __shfl_xor_sync(0xffffffffu, r0, s);
            u64 o1 = __shfl_xor_sync(0xffffffffu, r1, s);
            bool m0 = (((e0 & s) == 0) == ((e0 & k) == 0));
            bool m1 = (((e1 & s) == 0) == ((e1 & k) == 0));
            r0 = ((r0 < o0) == m0) ? r0 : o0;
            r1 = ((r1 < o1) == m1) ? r1 : o1;
        }
        if (k < TILE) {
            sv[tid] = r0;
            sv[tid + 1024] = r1;
            __syncthreads();
        }
    }
    g_ckey[tb + tid] = r0;
    g_ckey[tb + 1024 + tid] = r1;
}

// ---------------- kernel 2b: full k=4096 phase per 4096-half ----------------
__global__ void __launch_bounds__(1024) kphase4096_kernel() {
    __shared__ u64 sv[4096];
    int base = blockIdx.x << 12;
    int tid = threadIdx.x;
    int V = g_V;
    // V<=2048: halves already sorted/padding; base>=V: pure padding half
    if (V <= 2048 || base >= V) return;

#pragma unroll
    for (int i = 0; i < 4; i++) sv[tid + i * 1024] = g_ckey[base + tid + i * 1024];
    __syncthreads();

    bool up = ((base & 4096) == 0);        // uniform direction per block
    for (int s = 2048; s >= 32; s >>= 1) {
#pragma unroll
        for (int i = 0; i < 2; i++) {
            int v = tid + i * 1024;
            int a = ((v & ~(s - 1)) << 1) | (v & (s - 1));
            u64 x = sv[a], y = sv[a + s];
            if ((x > y) == up) { sv[a] = y; sv[a + s] = x; }
        }
        __syncthreads();
    }
    u64 r0 = sv[tid], r1 = sv[tid + 1024], r2 = sv[tid + 2048], r3 = sv[tid + 3072];
#pragma unroll
    for (int s = 16; s >= 1; s >>= 1) {
        u64 o0 = __shfl_xor_sync(0xffffffffu, r0, s);
        u64 o1 = __shfl_xor_sync(0xffffffffu, r1, s);
        u64 o2 = __shfl_xor_sync(0xffffffffu, r2, s);
        u64 o3 = __shfl_xor_sync(0xffffffffu, r3, s);
        bool m = (((tid & s) == 0) == up);  // low bits of element == low bits of tid
        r0 = ((r0 < o0) == m) ? r0 : o0;
        r1 = ((r1 < o1) == m) ? r1 : o1;
        r2 = ((r2 < o2) == m) ? r2 : o2;
        r3 = ((r3 < o3) == m) ? r3 : o3;
    }
    g_ckey[base + tid] = r0;
    g_ckey[base + tid + 1024] = r1;
    g_ckey[base + tid + 2048] = r2;
    g_ckey[base + tid + 3072] = r3;
}

// ---------------- kernel 2c: full k=8192 merge phase (skipped if V<=4096) ---
extern "C" __global__ void __launch_bounds__(1024) kphase8192_kernel() {
    extern __shared__ u64 sv8[];           // 64KB dynamic
    int tid = threadIdx.x;
    int V = g_V;
    if (V <= 4096) return;                 // first 4096 already fully ascending

#pragma unroll
    for (int i = 0; i < 8; i++) sv8[tid + i * 1024] = g_ckey[tid + i * 1024];
    __syncthreads();
    for (int s = 4096; s >= 32; s >>= 1) {
#pragma unroll
        for (int i = 0; i < 4; i++) {
            int v = tid + i * 1024;
            int a = ((v & ~(s - 1)) << 1) | (v & (s - 1));
            u64 x = sv8[a], y = sv8[a + s];
            if (x > y) { sv8[a] = y; sv8[a + s] = x; }   // up = true globally
        }
        __syncthreads();
    }
    u64 r[8];
#pragma unroll
    for (int i = 0; i < 8; i++) r[i] = sv8[tid + i * 1024];
#pragma unroll
    for (int s = 16; s >= 1; s >>= 1) {
        bool m = ((tid & s) == 0);
#pragma unroll
        for (int i = 0; i < 8; i++) {
            u64 o = __shfl_xor_sync(0xffffffffu, r[i], s);
            r[i] = ((r[i] < o) == m) ? r[i] : o;
        }
    }
#pragma unroll
    for (int i = 0; i < 8; i++) g_ckey[tid + i * 1024] = r[i];
}

// ---------------- kernel 2d: multi-block gather (sorted rows + boxes) -------
__global__ void __launch_bounds__(256) gather_kernel() {
    int j = blockIdx.x * 256 + threadIdx.x;
    int V = g_V;
    if (j >= V) return;
    int idx = (int)(g_ckey[j] & 0x1FFFu);
    float dd[5];
#pragma unroll
    for (int c = 0; c < 5; c++) {
        dd[c] = g_d[idx * 5 + c];
        g_ds[j * 5 + c] = dd[c];
    }
    g_boxes[j] = make_float4(dd[1] - 0.5f * dd[3], dd[2] - 0.5f * dd[4],
                             dd[1] + 0.5f * dd[3], dd[2] + 0.5f * dd[4]);
}

// ---------------- kernel 3: IoU bitmask (256 rows x 64 cols per block) ------
__global__ void __launch_bounds__(256) mask_kernel() {
    int bx = blockIdx.x;                       // column word 0..127
    int by = blockIdx.y;                       // row tile 0..31 (256 rows each)
    int V = g_V;
    if ((by << 8) >= V || (bx << 6) >= V) return;
    if (bx < (by << 2)) return;                // tile entirely i <= j

    __shared__ float4 cbox[64];
    __shared__ float  carea[64];
    int t = threadIdx.x;
    if (t < 64) {
        int ci = (bx << 6) + t;
        float4 cb = (ci < V) ? g_boxes[ci] : make_float4(0.f, 0.f, 0.f, 0.f);
        cbox[t] = cb;
        carea[t] = fmaxf(cb.z - cb.x, 0.f) * fmaxf(cb.w - cb.y, 0.f);
    }
    __syncthreads();

    int j = (by << 8) + t;
    if (j >= V) return;
    float4 rb = g_boxes[j];
    float  ra = fmaxf(rb.z - rb.x, 0.f) * fmaxf(rb.w - rb.y, 0.f);

    u64 bits = 0ull;
#pragma unroll
    for (int b = 0; b < 64; b++) {
        int i = (bx << 6) + b;
        if (i > j) {
            float iw = fmaxf(fminf(rb.z, cbox[b].z) - fmaxf(rb.x, cbox[b].x), 0.f);
            float ih = fmaxf(fminf(rb.w, cbox[b].w) - fmaxf(rb.y, cbox[b].y), 0.f);
            float inter = iw * ih;
            float uni = ra + carea[b] - inter;
            if (inter > NMS_T * fmaxf(uni, 1e-9f)) bits |= (1ull << b);
        }
    }
    g_mask[(size_t)j * NW + bx] = bits;
}

// interleaved 4-way u64 warp OR-reduce
#define RED4(q0, q1, q2, q3)                                          \
    _Pragma("unroll")                                                 \
    for (int s_ = 16; s_ >= 1; s_ >>= 1) {                            \
        q0 |= __shfl_xor_sync(0xffffffffu, q0, s_);                   \
        q1 |= __shfl_xor_sync(0xffffffffu, q1, s_);                   \
        q2 |= __shfl_xor_sync(0xffffffffu, q2, s_);                   \
        q3 |= __shfl_xor_sync(0xffffffffu, q3, s_);                   \
    }

// ---------------- kernel 4: warp-cooperative greedy NMS scan + output -------
__global__ void __launch_bounds__(512) scan_kernel(float* __restrict__ out) {
    __shared__ u64 remv[NW];
    __shared__ u64 skeep[NW];
    __shared__ u64 sdiag[CH][WPC];        // 8KB diagonal block
    __shared__ u64 part[512];
    __shared__ unsigned short klist[CH];
    __shared__ int knum;
    int t = threadIdx.x;
    int V = g_V;
    int NC = (V + CH - 1) / CH;
    int NWv = (V + 63) >> 6;

    if (t == 511) g_cnt = 0;              // deterministic reset for next replay
    if (t < NW) { remv[t] = 0ull; skeep[t] = 0ull; }
    part[t] = 0ull;

    // prefetch diag block of chunk 0 (row = i>>2, word = i&3)
    u64 d0 = 0ull, d1 = 0ull;
    if (NC > 0) {
        d0 = g_mask[(size_t)(t >> 2) * NW + (t & 3)];
        d1 = g_mask[(size_t)((t + 512) >> 2) * NW + ((t + 512) & 3)];
    }
    __syncthreads();

    for (int c = 0; c < NC; c++) {
        sdiag[t >> 2][t & 3] = d0;
        sdiag[(t + 512) >> 2][(t + 512) & 3] = d1;
        // fold prev chunk's propagation partials into remv (word c*WPC + t)
        if (t < NW) {
            int w = c * WPC + t;
            if (w < NW)
                remv[w] |= (part[t * 4] | part[t * 4 + 1]) |
                           (part[t * 4 + 2] | part[t * 4 + 3]);
        }
        __syncthreads();

        // prefetch next chunk's diag block
        if (c + 1 < NC) {
            int base = (c + 1) * CH;
            d0 = g_mask[(size_t)(base + (t >> 2)) * NW + ((c + 1) * WPC + (t & 3))];
            d1 = g_mask[(size_t)(base + ((t + 512) >> 2)) * NW +
                        ((c + 1) * WPC + ((t + 512) & 3))];
        }

        if (t < 32) {
            // warp-cooperative optimistic greedy (exact semantics)
            int lane = t;
            u64 ss1 = 0ull, ss2 = 0ull, ss3 = 0ull;   // cross-word (uniform)
            int nk = 0;
#pragma unroll
            for (int w = 0; w < WPC; w++) {
                int gw = c * WPC + w;
                int rbnd = V - (gw << 6);
                u64 vm = (rbnd >= 64) ? ~0ull
                                      : (rbnd <= 0 ? 0ull : ((1ull << rbnd) - 1ull));
                u64 ssw = (w == 1) ? ss1 : (w == 2) ? ss2 : (w == 3) ? ss3 : 0ull;
                u64 rem = (~remv[gw]) & vm & ~ssw;
                u64 kept = 0ull;
                while (rem) {
                    bool h0 = (rem >> lane) & 1ull;
                    bool h1 = (rem >> (lane + 32)) & 1ull;
                    u64 r00 = 0, r01 = 0, r02 = 0, r03 = 0;
                    u64 r10 = 0, r11 = 0, r12 = 0, r13 = 0;
                    if (h0) {
                        const u64* rp = sdiag[(w << 6) + lane];
                        r00 = rp[0]; r01 = rp[1]; r02 = rp[2]; r03 = rp[3];
                    }
                    if (h1) {
                        const u64* rp = sdiag[(w << 6) + lane + 32];
                        r10 = rp[0]; r11 = rp[1]; r12 = rp[2]; r13 = rp[3];
                    }
                    u64 q0 = r00 | r10, q1 = r01 | r11;
                    u64 q2 = r02 | r12, q3 = r03 | r13;
                    RED4(q0, q1, q2, q3);
                    u64 Sw = (w == 0) ? q0 : (w == 1) ? q1 : (w == 2) ? q2 : q3;
                    u64 C = rem & Sw;
                    if (C == 0ull) {
                        kept |= rem;
                        if (w < 1) ss1 |= q1;
                        if (w < 2) ss2 |= q2;
                        if (w < 3) ss3 |= q3;
                        rem = 0ull;
                    } else {
                        int fc = __ffsll((long long)C) - 1;
                        u64 below = (1ull << fc) - 1ull;
                        kept |= rem & below;
                        // reduce restricted to committed (bit < fc) rows
                        bool c0 = h0 && (lane < fc);
                        bool c1 = h1 && (lane + 32 < fc);
                        u64 p0 = (c0 ? r00 : 0ull) | (c1 ? r10 : 0ull);
                        u64 p1 = (c0 ? r01 : 0ull) | (c1 ? r11 : 0ull);
                        u64 p2 = (c0 ? r02 : 0ull) | (c1 ? r12 : 0ull);
                        u64 p3 = (c0 ? r03 : 0ull) | (c1 ? r13 : 0ull);
                        RED4(p0, p1, p2, p3);
                        if (w < 1) ss1 |= p1;
                        if (w < 2) ss2 |= p2;
                        if (w < 3) ss3 |= p3;
                        u64 pw = (w == 0) ? p0 : (w == 1) ? p1 : (w == 2) ? p2 : p3;
                        rem = rem & ~((2ull << fc) - 1ull) & ~pw;
                    }
                }
                // record kept: skeep + warp-parallel klist fill (rank by popc)
                if (lane == 0) skeep[gw] = kept;
                if ((kept >> lane) & 1ull) {
                    int pos = nk + (int)__popcll(kept & ((1ull << lane) - 1ull));
                    klist[pos] = (unsigned short)((w << 6) + lane);
                }
                int l2 = lane + 32;
                if ((kept >> l2) & 1ull) {
                    int pos = nk + (int)__popcll(kept & ((1ull << l2) - 1ull));
                    klist[pos] = (unsigned short)((w << 6) + l2);
                }
                nk += (int)__popcll(kept);
                __syncwarp();
            }
            if (lane == 0) knum = nk;
        }
        __syncthreads();

        // propagation: 4 threads per word, 4 accumulators (MLP 16/word)
        {
            int w = (c + 1) * WPC + (t >> 2);
            int sub = t & 3;
            u64 a0 = 0ull, a1 = 0ull, a2 = 0ull, a3 = 0ull;
            if (w < NWv) {
                const u64* bp = g_mask + (size_t)(c * CH) * NW + w;
                int n = knum;
                int i = sub;
                for (; i + 12 < n; i += 16) {
                    a0 |= bp[(size_t)klist[i] * NW];
                    a1 |= bp[(size_t)klist[i + 4] * NW];
                    a2 |= bp[(size_t)klist[i + 8] * NW];
                    a3 |= bp[(size_t)klist[i + 12] * NW];
                }
                for (; i < n; i += 4) a0 |= bp[(size_t)klist[i] * NW];
            }
            part[t] = (a0 | a1) | (a2 | a3);
        }
        __syncthreads();
    }

    // fused masked output
    for (int j = t; j < M; j += 512) {
        if (j < V) {
            float f = ((skeep[j >> 6] >> (j & 63)) & 1ull) ? 1.0f : 0.0f;
#pragma unroll
            for (int c5 = 0; c5 < 5; c5++)
                out[j * 5 + c5] = g_ds[j * 5 + c5] * f;
        } else {
#pragma unroll
            for (int c5 = 0; c5 < 5; c5++)
                out[j * 5 + c5] = 0.0f;
        }
    }
}

// ---------------- launcher ---------------------------------------------------
extern "C" void kernel_launch(void* const* d_in, const int* in_sizes, int n_in,
                              void* d_out, int out_size) {
    const float* det = (const float*)d_in[0];
    const float* off = (const float*)d_in[1];
    const float* scl = (const float*)d_in[2];
    const float* bnd = (const float*)d_in[3];
    float* out = (float*)d_out;

    cudaFuncSetAttribute((const void*)kphase8192_kernel,
                         cudaFuncAttributeMaxDynamicSharedMemorySize, 65536);

    prep_kernel<<<32, 256>>>(det, off, scl, bnd);
    lsort_kernel<<<NTILE, 1024>>>();
    kphase4096_kernel<<<2, 1024>>>();
    kphase8192_kernel<<<1, 1024, 65536>>>();
    gather_kernel<<<32, 256>>>();
    mask_kernel<<<dim3(NW, 32), 256>>>();
    scan_kernel<<<1, 512>>>(out);
}

// round 16
// speedup vs baseline: 1.0331x; 1.0331x over previous
#include <cuda_runtime.h>
#include <cstdint>

#define M 8192
#define NW 128          // 64-bit words per row (M/64)
#define NMS_T 0.3f
#define CH 256          // scan chunk size (elements)
#define WPC 4           // words per chunk (CH/64)
#define TILE 2048       // sort tile size
#define NTILE 4         // number of sort tiles (M/TILE)

typedef unsigned long long u64;

// ---------------- device scratch (no runtime allocation allowed) ------------
__device__ float  g_d[M * 5];        // transformed detections (orig order)
__device__ u64    g_ckey[M];         // packed (key<<13 | idx), all 8192 rows
__device__ int    g_cnt;             // valid count (atomic; reset by scan)
__device__ int    g_V;               // valid count (published by kphase4096)
__device__ float  g_ds[M * 5];       // sorted detections (first V rows)
__device__ float4 g_boxes[M];        // x1,y1,x2,y2 (sorted order, first V)
__device__ u64    g_mask[M * NW];    // suppression bitmask (i>j bits only)

// ---------------- kernel 1: fused transform + key-build + 2048-tile sort ----
// No compaction: invalid rows get key 0xFFFFFFFF (> any valid key) and sort
// to the tail; the first V sorted entries are exactly the valid ones.
__global__ void __launch_bounds__(1024) lsortprep_kernel(
        const float* __restrict__ det, const float* __restrict__ off,
        const float* __restrict__ scl, const float* __restrict__ bnd) {
    __shared__ u64 sv[TILE];
    __shared__ float srow[1024 * 5];       // staging for one 1024-row half
    int tb = blockIdx.x << 11;
    int tid = threadIdx.x;
    int lane = tid & 31;

#pragma unroll
    for (int half = 0; half < 2; half++) {
        int rowbase = tb + (half << 10);
        const float* src = det + (size_t)rowbase * 5;
        for (int i = tid; i < 1024 * 5; i += 1024) srow[i] = src[i];
        __syncthreads();

        int i = rowbase + tid;             // global row
        int w = i >> 10;                   // uniform within this half
        float a0 = srow[tid * 5 + 0], a1 = srow[tid * 5 + 1];
        float a2 = srow[tid * 5 + 2], a3 = srow[tid * 5 + 3];
        float a4 = srow[tid * 5 + 4];
        float d0 = off[w * 5 + 0] + a0 * scl[w * 5 + 0];
        float d1 = off[w * 5 + 1] + a1 * scl[w * 5 + 1];
        float d2 = off[w * 5 + 2] + a2 * scl[w * 5 + 2];
        float d3 = off[w * 5 + 3] + a3 * scl[w * 5 + 3];
        float d4 = off[w * 5 + 4] + a4 * scl[w * 5 + 4];
        bool valid = (a1 < bnd[w * 4 + 1]) && (a1 > bnd[w * 4 + 0]) &&
                     (a2 < bnd[w * 4 + 3]) && (a2 > bnd[w * 4 + 2]);

        g_d[i * 5 + 0] = d0;
        g_d[i * 5 + 1] = d1;
        g_d[i * 5 + 2] = d2;
        g_d[i * 5 + 3] = d3;
        g_d[i * 5 + 4] = d4;

        bool take = valid && d0 > 0.0f;    // non-positive scores -> zero rows
        // valid key = ~(bits|sign) <= 0x7FFFFFFF; invalid = 0xFFFFFFFF
        unsigned key = take ? ~(__float_as_uint(d0) | 0x80000000u) : 0xFFFFFFFFu;
        sv[(half << 10) + tid] = ((u64)key << 13) | (u64)i;  // (score desc, idx asc)

        unsigned ball = __ballot_sync(0xffffffffu, take);
        if (lane == 0 && ball) atomicAdd(&g_cnt, __popc(ball));
        __syncthreads();
    }

    u64 r0 = sv[tid];
    u64 r1 = sv[tid + 1024];

    // phase A: k = 2..32 entirely in registers (intra-warp shuffles)
    int e0 = tb + tid, e1 = tb + 1024 + tid;
#pragma unroll
    for (int k = 2; k <= 32; k <<= 1) {
#pragma unroll
        for (int s = k >> 1; s >= 1; s >>= 1) {
            u64 o0 = __shfl_xor_sync(0xffffffffu, r0, s);
            u64 o1 = __shfl_xor_sync(0xffffffffu, r1, s);
            bool m0 = (((e0 & s) == 0) == ((e0 & k) == 0));
            bool m1 = (((e1 & s) == 0) == ((e1 & k) == 0));
            r0 = ((r0 < o0) == m0) ? r0 : o0;
            r1 = ((r1 < o1) == m1) ? r1 : o1;
        }
    }
    sv[tid] = r0;
    sv[tid + 1024] = r1;
    __syncthreads();

    // phase B: k = 64..2048 (strides >=32 in smem, <=16 via shuffles)
#pragma unroll
    for (int k = 64; k <= TILE; k <<= 1) {
        for (int s = k >> 1; s >= 32; s >>= 1) {
            int a = ((tid & ~(s - 1)) << 1) | (tid & (s - 1));
            bool up = (((tb + a) & k) == 0);
            u64 x = sv[a], y = sv[a + s];
            if ((x > y) == up) { sv[a] = y; sv[a + s] = x; }
            __syncthreads();
        }
        r0 = sv[tid];
        r1 = sv[tid + 1024];
#pragma unroll
        for (int s = 16; s >= 1; s >>= 1) {
            u64 o0 = __shfl_xor_sync(0xffffffffu, r0, s);
            u64 o1 = __shfl_xor_sync(0xffffffffu, r1, s);
            bool m0 = (((e0 & s) == 0) == ((e0 & k) == 0));
            bool m1 = (((e1 & s) == 0) == ((e1 & k) == 0));
            r0 = ((r0 < o0) == m0) ? r0 : o0;
            r1 = ((r1 < o1) == m1) ? r1 : o1;
        }
        if (k < TILE) {
            sv[tid] = r0;
            sv[tid + 1024] = r1;
            __syncthreads();
        }
    }
    g_ckey[tb + tid] = r0;
    g_ckey[tb + 1024 + tid] = r1;
}

// ---------------- kernel 2a: full k=4096 phase per 4096-half ----------------
__global__ void __launch_bounds__(1024) kphase4096_kernel() {
    __shared__ u64 sv[4096];
    int base = blockIdx.x << 12;
    int tid = threadIdx.x;
    if (base == 0 && tid == 0) g_V = g_cnt;   // publish valid count

#pragma unroll
    for (int i = 0; i < 4; i++) sv[tid + i * 1024] = g_ckey[base + tid + i * 1024];
    __syncthreads();

    bool up = ((base & 4096) == 0);        // uniform direction per block
    for (int s = 2048; s >= 32; s >>= 1) {
#pragma unroll
        for (int i = 0; i < 2; i++) {
            int v = tid + i * 1024;
            int a = ((v & ~(s - 1)) << 1) | (v & (s - 1));
            u64 x = sv[a], y = sv[a + s];
            if ((x > y) == up) { sv[a] = y; sv[a + s] = x; }
        }
        __syncthreads();
    }
    u64 r0 = sv[tid], r1 = sv[tid + 1024], r2 = sv[tid + 2048], r3 = sv[tid + 3072];
#pragma unroll
    for (int s = 16; s >= 1; s >>= 1) {
        u64 o0 = __shfl_xor_sync(0xffffffffu, r0, s);
        u64 o1 = __shfl_xor_sync(0xffffffffu, r1, s);
        u64 o2 = __shfl_xor_sync(0xffffffffu, r2, s);
        u64 o3 = __shfl_xor_sync(0xffffffffu, r3, s);
        bool m = (((tid & s) == 0) == up);
        r0 = ((r0 < o0) == m) ? r0 : o0;
        r1 = ((r1 < o1) == m) ? r1 : o1;
        r2 = ((r2 < o2) == m) ? r2 : o2;
        r3 = ((r3 < o3) == m) ? r3 : o3;
    }
    g_ckey[base + tid] = r0;
    g_ckey[base + tid + 1024] = r1;
    g_ckey[base + tid + 2048] = r2;
    g_ckey[base + tid + 3072] = r3;
}

// ---------------- kernel 2b: full k=8192 merge phase (always runs) ----------
extern "C" __global__ void __launch_bounds__(1024) kphase8192_kernel() {
    extern __shared__ u64 sv8[];           // 64KB dynamic
    int tid = threadIdx.x;

#pragma unroll
    for (int i = 0; i < 8; i++) sv8[tid + i * 1024] = g_ckey[tid + i * 1024];
    __syncthreads();
    for (int s = 4096; s >= 32; s >>= 1) {
#pragma unroll
        for (int i = 0; i < 4; i++) {
            int v = tid + i * 1024;
            int a = ((v & ~(s - 1)) << 1) | (v & (s - 1));
            u64 x = sv8[a], y = sv8[a + s];
            if (x > y) { sv8[a] = y; sv8[a + s] = x; }   // up = true globally
        }
        __syncthreads();
    }
    u64 r[8];
#pragma unroll
    for (int i = 0; i < 8; i++) r[i] = sv8[tid + i * 1024];
#pragma unroll
    for (int s = 16; s >= 1; s >>= 1) {
        bool m = ((tid & s) == 0);
#pragma unroll
        for (int i = 0; i < 8; i++) {
            u64 o = __shfl_xor_sync(0xffffffffu, r[i], s);
            r[i] = ((r[i] < o) == m) ? r[i] : o;
        }
    }
#pragma unroll
    for (int i = 0; i < 8; i++) g_ckey[tid + i * 1024] = r[i];
}

// ---------------- kernel 2c: multi-block gather (sorted rows + boxes) -------
__global__ void __launch_bounds__(256) gather_kernel() {
    int j = blockIdx.x * 256 + threadIdx.x;
    int V = g_V;
    if (j >= V) return;
    int idx = (int)(g_ckey[j] & 0x1FFFu);
    float dd[5];
#pragma unroll
    for (int c = 0; c < 5; c++) {
        dd[c] = g_d[idx * 5 + c];
        g_ds[j * 5 + c] = dd[c];
    }
    g_boxes[j] = make_float4(dd[1] - 0.5f * dd[3], dd[2] - 0.5f * dd[4],
                             dd[1] + 0.5f * dd[3], dd[2] + 0.5f * dd[4]);
}

// ---------------- kernel 3: IoU bitmask (256 rows x 64 cols per block) ------
__global__ void __launch_bounds__(256) mask_kernel() {
    int bx = blockIdx.x;                       // column word 0..127
    int by = blockIdx.y;                       // row tile 0..31 (256 rows each)
    int V = g_V;
    if ((by << 8) >= V || (bx << 6) >= V) return;
    if (bx < (by << 2)) return;                // tile entirely i <= j

    __shared__ float4 cbox[64];
    __shared__ float  carea[64];
    int t = threadIdx.x;
    if (t < 64) {
        int ci = (bx << 6) + t;
        float4 cb = (ci < V) ? g_boxes[ci] : make_float4(0.f, 0.f, 0.f, 0.f);
        cbox[t] = cb;
        carea[t] = fmaxf(cb.z - cb.x, 0.f) * fmaxf(cb.w - cb.y, 0.f);
    }
    __syncthreads();

    int j = (by << 8) + t;
    if (j >= V) return;
    float4 rb = g_boxes[j];
    float  ra = fmaxf(rb.z - rb.x, 0.f) * fmaxf(rb.w - rb.y, 0.f);

    u64 bits = 0ull;
#pragma unroll
    for (int b = 0; b < 64; b++) {
        int i = (bx << 6) + b;
        if (i > j) {
            float iw = fmaxf(fminf(rb.z, cbox[b].z) - fmaxf(rb.x, cbox[b].x), 0.f);
            float ih = fmaxf(fminf(rb.w, cbox[b].w) - fmaxf(rb.y, cbox[b].y), 0.f);
            float inter = iw * ih;
            float uni = ra + carea[b] - inter;
            if (inter > NMS_T * fmaxf(uni, 1e-9f)) bits |= (1ull << b);
        }
    }
    g_mask[(size_t)j * NW + bx] = bits;
}

// ---------------- kernel 4: greedy NMS scan (R8 exact) + fused output -------
__global__ void __launch_bounds__(512) scan_kernel(float* __restrict__ out) {
    __shared__ u64 remv[NW];
    __shared__ u64 skeep[NW];
    __shared__ u64 sdiag[CH][WPC];        // 8KB diagonal block
    __shared__ u64 part[512];
    __shared__ unsigned short klist[CH];
    __shared__ int knum;
    int t = threadIdx.x;
    int V = g_V;
    int NC = (V + CH - 1) / CH;
    int NWv = (V + 63) >> 6;

    if (t == 511) g_cnt = 0;              // deterministic reset for next replay
    if (t < NW) { remv[t] = 0ull; skeep[t] = 0ull; }
    part[t] = 0ull;

    // prefetch diag block of chunk 0 (row = i>>2, word = i&3)
    u64 d0 = 0ull, d1 = 0ull;
    if (NC > 0) {
        d0 = g_mask[(size_t)(t >> 2) * NW + (t & 3)];
        d1 = g_mask[(size_t)((t + 512) >> 2) * NW + ((t + 512) & 3)];
    }
    __syncthreads();

    for (int c = 0; c < NC; c++) {
        sdiag[t >> 2][t & 3] = d0;
        sdiag[(t + 512) >> 2][(t + 512) & 3] = d1;
        // fold prev chunk's propagation partials into remv (word c*WPC + t)
        if (t < NW) {
            int w = c * WPC + t;
            if (w < NW)
                remv[w] |= (part[t * 4] | part[t * 4 + 1]) |
                           (part[t * 4 + 2] | part[t * 4 + 3]);
        }
        __syncthreads();

        // prefetch next chunk's diag block
        if (c + 1 < NC) {
            int base = (c + 1) * CH;
            d0 = g_mask[(size_t)(base + (t >> 2)) * NW + ((c + 1) * WPC + (t & 3))];
            d1 = g_mask[(size_t)(base + ((t + 512) >> 2)) * NW +
                        ((c + 1) * WPC + ((t + 512) & 3))];
        }

        if (t == 0) {
            // simple greedy: EXACT R4/R8 loop (spill-sensitive, do not touch)
            u64 alive[WPC], kept[WPC];
#pragma unroll
            for (int u = 0; u < WPC; u++) {
                int rb = V - ((c * WPC + u) << 6);
                u64 vm = (rb >= 64) ? ~0ull : (rb <= 0 ? 0ull : ((1ull << rb) - 1ull));
                alive[u] = ~remv[c * WPC + u] & vm;
                kept[u] = 0ull;
            }
            int n = 0;
            for (int w = 0; w < WPC; w++) {
                while (alive[w]) {
                    int b = __ffsll((long long)alive[w]) - 1;
                    int rr = (w << 6) + b;
                    kept[w] |= 1ull << b;
                    klist[n++] = (unsigned short)rr;
                    alive[w] &= ~(1ull << b);
                    for (int u = w; u < WPC; u++)
                        alive[u] &= ~sdiag[rr][u];
                }
            }
#pragma unroll
            for (int u = 0; u < WPC; u++) skeep[c * WPC + u] = kept[u];
            knum = n;
        }
        __syncthreads();

        // propagation: 4 threads per word, 4 accumulators (MLP 16/word)
        {
            int w = (c + 1) * WPC + (t >> 2);
            int sub = t & 3;
            u64 a0 = 0ull, a1 = 0ull, a2 = 0ull, a3 = 0ull;
            if (w < NWv) {
                const u64* bp = g_mask + (size_t)(c * CH) * NW + w;
                int n = knum;
                int i = sub;
                for (; i + 12 < n; i += 16) {
                    a0 |= bp[(size_t)klist[i] * NW];
                    a1 |= bp[(size_t)klist[i + 4] * NW];
                    a2 |= bp[(size_t)klist[i + 8] * NW];
                    a3 |= bp[(size_t)klist[i + 12] * NW];
                }
                for (; i < n; i += 4) a0 |= bp[(size_t)klist[i] * NW];
            }
            part[t] = (a0 | a1) | (a2 | a3);
        }
        __syncthreads();
    }

    // fused masked output
    for (int j = t; j < M; j += 512) {
        if (j < V) {
            float f = ((skeep[j >> 6] >> (j & 63)) & 1ull) ? 1.0f : 0.0f;
#pragma unroll
            for (int c5 = 0; c5 < 5; c5++)
                out[j * 5 + c5] = g_ds[j * 5 + c5] * f;
        } else {
#pragma unroll
            for (int c5 = 0; c5 < 5; c5++)
                out[j * 5 + c5] = 0.0f;
        }
    }
}

// ---------------- launcher ---------------------------------------------------
extern "C" void kernel_launch(void* const* d_in, const int* in_sizes, int n_in,
                              void* d_out, int out_size) {
    const float* det = (const float*)d_in[0];
    const float* off = (const float*)d_in[1];
    const float* scl = (const float*)d_in[2];
    const float* bnd = (const float*)d_in[3];
    float* out = (float*)d_out;

    cudaFuncSetAttribute((const void*)kphase8192_kernel,
                         cudaFuncAttributeMaxDynamicSharedMemorySize, 65536);

    lsortprep_kernel<<<NTILE, 1024>>>(det, off, scl, bnd);
    kphase4096_kernel<<<2, 1024>>>();
    kphase8192_kernel<<<1, 1024, 65536>>>();
    gather_kernel<<<32, 256>>>();
    mask_kernel<<<dim3(NW, 32), 256>>>();
    scan_kernel<<<1, 512>>>(out);
}

// round 17
// speedup vs baseline: 1.1594x; 1.1222x over previous
#include <cuda_runtime.h>
#include <cstdint>

#define M 8192
#define NW 128          // 64-bit words per row (M/64)
#define NMS_T 0.3f
#define CH 256          // scan chunk size (elements)
#define WPC 4           // words per chunk (CH/64)
#define TILE 2048       // sort tile size
#define NTILE 4         // number of sort tiles (M/TILE)

typedef unsigned long long u64;

// ---------------- device scratch (no runtime allocation allowed) ------------
__device__ float  g_d[M * 5];        // transformed detections (orig order)
__device__ u64    g_ckey[M];         // packed (key<<13 | idx), padded to 8192
__device__ int    g_cnt;             // valid count (atomic; reset by scan)
__device__ int    g_V;               // valid count (published by lsort)
__device__ float  g_ds[M * 5];       // sorted detections (first V rows)
__device__ float4 g_boxes[M];        // x1,y1,x2,y2 (sorted order, first V)
__device__ u64    g_mask[M * NW];    // suppression bitmask (i>j bits only)

// ---------------- kernel 1: transform + score + compact (coalesced) ---------
__global__ void __launch_bounds__(256)
prep_kernel(const float* __restrict__ det, const float* __restrict__ off,
            const float* __restrict__ scl, const float* __restrict__ bnd) {
    __shared__ float srow[256 * 5];
    int b = blockIdx.x;                    // 32 blocks x 256 rows
    int tid = threadIdx.x;
    int lane = tid & 31;
    const float* src = det + b * 256 * 5;
    for (int i = tid; i < 256 * 5; i += 256) srow[i] = src[i];
    __syncthreads();

    int i = b * 256 + tid;                 // global row
    int w = i >> 10;
    float a0 = srow[tid * 5 + 0], a1 = srow[tid * 5 + 1], a2 = srow[tid * 5 + 2];
    float a3 = srow[tid * 5 + 3], a4 = srow[tid * 5 + 4];
    float d0 = off[w * 5 + 0] + a0 * scl[w * 5 + 0];
    float d1 = off[w * 5 + 1] + a1 * scl[w * 5 + 1];
    float d2 = off[w * 5 + 2] + a2 * scl[w * 5 + 2];
    float d3 = off[w * 5 + 3] + a3 * scl[w * 5 + 3];
    float d4 = off[w * 5 + 4] + a4 * scl[w * 5 + 4];
    bool valid = (a1 < bnd[w * 4 + 1]) && (a1 > bnd[w * 4 + 0]) &&
                 (a2 < bnd[w * 4 + 3]) && (a2 > bnd[w * 4 + 2]);

    g_d[i * 5 + 0] = d0;
    g_d[i * 5 + 1] = d1;
    g_d[i * 5 + 2] = d2;
    g_d[i * 5 + 3] = d3;
    g_d[i * 5 + 4] = d4;

    bool take = valid && d0 > 0.0f;        // non-positive scores -> zero rows
    unsigned ball = __ballot_sync(0xffffffffu, take);
    if (ball) {
        int nb = __popc(ball);
        int leader = __ffs(ball) - 1;
        int base = 0;
        if (lane == leader) base = atomicAdd(&g_cnt, nb);
        base = __shfl_sync(0xffffffffu, base, leader);
        if (take) {
            int o = __popc(ball & ((1u << lane) - 1));
            unsigned key = ~(__float_as_uint(d0) | 0x80000000u);
            g_ckey[base + o] = ((u64)key << 13) | (u64)i;  // (score desc, idx asc)
        }
    }
}

// ---------------- kernel 2a: local bitonic sort of 2048-tiles ---------------
__global__ void __launch_bounds__(1024) lsort_kernel() {
    __shared__ u64 sv[TILE];
    int tb = blockIdx.x << 11;
    int tid = threadIdx.x;
    int V = g_cnt;
    if (tb == 0 && tid == 0) g_V = V;

    if (tb >= V) {                         // pure padding tile: just materialize
        g_ckey[tb + tid] = ~0ull;
        g_ckey[tb + tid + 1024] = ~0ull;
        return;
    }

    u64 r0 = (tb + tid < V) ? g_ckey[tb + tid] : ~0ull;
    u64 r1 = (tb + tid + 1024 < V) ? g_ckey[tb + tid + 1024] : ~0ull;

    // phase A: k = 2..32 entirely in registers (intra-warp shuffles)
    int e0 = tb + tid, e1 = tb + 1024 + tid;
#pragma unroll
    for (int k = 2; k <= 32; k <<= 1) {
#pragma unroll
        for (int s = k >> 1; s >= 1; s >>= 1) {
            u64 o0 = __shfl_xor_sync(0xffffffffu, r0, s);
            u64 o1 = __shfl_xor_sync(0xffffffffu, r1, s);
            bool m0 = (((e0 & s) == 0) == ((e0 & k) == 0));
            bool m1 = (((e1 & s) == 0) == ((e1 & k) == 0));
            r0 = ((r0 < o0) == m0) ? r0 : o0;
            r1 = ((r1 < o1) == m1) ? r1 : o1;
        }
    }
    sv[tid] = r0;
    sv[tid + 1024] = r1;
    __syncthreads();

    // phase B: k = 64..2048 (strides >=32 in smem, <=16 via shuffles)
#pragma unroll
    for (int k = 64; k <= TILE; k <<= 1) {
        for (int s = k >> 1; s >= 32; s >>= 1) {
            int a = ((tid & ~(s - 1)) << 1) | (tid & (s - 1));
            bool up = (((tb + a) & k) == 0);
            u64 x = sv[a], y = sv[a + s];
            if ((x > y) == up) { sv[a] = y; sv[a + s] = x; }
            __syncthreads();
        }
        r0 = sv[tid];
        r1 = sv[tid + 1024];
#pragma unroll
        for (int s = 16; s >= 1; s >>= 1) {
            u64 o0 = __shfl_xor_sync(0xffffffffu, r0, s);
            u64 o1 = __shfl_xor_sync(0xffffffffu, r1, s);
            bool m0 = (((e0 & s) == 0) == ((e0 & k) == 0));
            bool m1 = (((e1 & s) == 0) == ((e1 & k) == 0));
            r0 = ((r0 < o0) == m0) ? r0 : o0;
            r1 = ((r1 < o1) == m1) ? r1 : o1;
        }
        if (k < TILE) {
            sv[tid] = r0;
            sv[tid + 1024] = r1;
            __syncthreads();
        }
    }
    g_ckey[tb + tid] = r0;
    g_ckey[tb + 1024 + tid] = r1;
}

// -------- cluster helpers ----------------------------------------------------
__device__ __forceinline__ unsigned cluster_rank() {
    unsigned r;
    asm("mov.u32 %0, %%cluster_ctarank;" : "=r"(r));
    return r;
}
__device__ __forceinline__ unsigned smem_u32(const void* p) {
    unsigned a;
    asm("{ .reg .u64 t; cvta.to.shared.u64 t, %1; cvt.u32.u64 %0, t; }"
        : "=r"(a) : "l"(p));
    return a;
}
__device__ __forceinline__ u64 dsmem_ld(const void* p, unsigned rank) {
    unsigned a = smem_u32(p), r;
    asm("mapa.shared::cluster.u32 %0, %1, %2;" : "=r"(r) : "r"(a), "r"(rank));
    u64 v;
    asm("ld.shared::cluster.b64 %0, [%1];" : "=l"(v) : "r"(r));
    return v;
}
#define CLUSTER_SYNC() do {                                            \
    asm volatile("barrier.cluster.arrive.aligned;" ::: "memory");      \
    asm volatile("barrier.cluster.wait.aligned;" ::: "memory");        \
} while (0)

// ---------------- kernel 2b: fused k=4096 + (conditional) k=8192 phases -----
// cluster of 2 CTAs; CTA r owns half [r*4096, (r+1)*4096). When V<=4096 this
// is exactly the old kphase4096 (k=8192 merge skipped). When V>4096, the
// s=4096 stage runs via DSMEM exchange, then local s<=2048 stages per half.
__global__ void __cluster_dims__(2, 1, 1) __launch_bounds__(1024)
ksort_kernel() {
    __shared__ u64 sv[4096];               // 32KB
    unsigned rank = cluster_rank();
    int base = (int)rank << 12;
    int tid = threadIdx.x;
    int V = g_V;
    bool merge = (V > 4096);

    if (!merge && (V <= 2048 || base >= V))
        return;                            // half already sorted / pure padding

#pragma unroll
    for (int i = 0; i < 4; i++) sv[tid + i * 1024] = g_ckey[base + tid + i * 1024];
    __syncthreads();

    // ---- k=4096 phase on this half (direction alternates by half) ----
    {
        bool up = (rank == 0);
        for (int s = 2048; s >= 32; s >>= 1) {
#pragma unroll
            for (int i = 0; i < 2; i++) {
                int v = tid + i * 1024;
                int a = ((v & ~(s - 1)) << 1) | (v & (s - 1));
                u64 x = sv[a], y = sv[a + s];
                if ((x > y) == up) { sv[a] = y; sv[a + s] = x; }
            }
            __syncthreads();
        }
        u64 r0 = sv[tid], r1 = sv[tid + 1024];
        u64 r2 = sv[tid + 2048], r3 = sv[tid + 3072];
#pragma unroll
        for (int s = 16; s >= 1; s >>= 1) {
            u64 o0 = __shfl_xor_sync(0xffffffffu, r0, s);
            u64 o1 = __shfl_xor_sync(0xffffffffu, r1, s);
            u64 o2 = __shfl_xor_sync(0xffffffffu, r2, s);
            u64 o3 = __shfl_xor_sync(0xffffffffu, r3, s);
            bool m = (((tid & s) == 0) == up);
            r0 = ((r0 < o0) == m) ? r0 : o0;
            r1 = ((r1 < o1) == m) ? r1 : o1;
            r2 = ((r2 < o2) == m) ? r2 : o2;
            r3 = ((r3 < o3) == m) ? r3 : o3;
        }
        if (!merge) {                      // done: write back and exit
            g_ckey[base + tid] = r0;
            g_ckey[base + tid + 1024] = r1;
            g_ckey[base + tid + 2048] = r2;
            g_ckey[base + tid + 3072] = r3;
            return;
        }
        sv[tid] = r0;
        sv[tid + 1024] = r1;
        sv[tid + 2048] = r2;
        sv[tid + 3072] = r3;
        __syncthreads();
    }

    // ---- k=8192 merge: s=4096 stage via DSMEM exchange ----
    {
        unsigned peer = rank ^ 1u;
        u64 x0 = sv[tid],        y0 = dsmem_ld(&sv[tid], peer);
        u64 x1 = sv[tid + 1024], y1 = dsmem_ld(&sv[tid + 1024], peer);
        u64 x2 = sv[tid + 2048], y2 = dsmem_ld(&sv[tid + 2048], peer);
        u64 x3 = sv[tid + 3072], y3 = dsmem_ld(&sv[tid + 3072], peer);
        u64 n0, n1, n2, n3;
        if (rank == 0) {
            n0 = (x0 < y0) ? x0 : y0; n1 = (x1 < y1) ? x1 : y1;
            n2 = (x2 < y2) ? x2 : y2; n3 = (x3 < y3) ? x3 : y3;
        } else {
            n0 = (x0 < y0) ? y0 : x0; n1 = (x1 < y1) ? y1 : x1;
            n2 = (x2 < y2) ? y2 : x2; n3 = (x3 < y3) ? y3 : x3;
        }
        CLUSTER_SYNC();                    // all peer reads consumed above
        sv[tid] = n0;
        sv[tid + 1024] = n1;
        sv[tid + 2048] = n2;
        sv[tid + 3072] = n3;
        __syncthreads();
    }

    // ---- local stages s=2048..1, ascending, then write back ----
    for (int s = 2048; s >= 32; s >>= 1) {
#pragma unroll
        for (int i = 0; i < 2; i++) {
            int v = tid + i * 1024;
            int a = ((v & ~(s - 1)) << 1) | (v & (s - 1));
            u64 x = sv[a], y = sv[a + s];
            if (x > y) { sv[a] = y; sv[a + s] = x; }
        }
        __syncthreads();
    }
    {
        u64 r0 = sv[tid], r1 = sv[tid + 1024];
        u64 r2 = sv[tid + 2048], r3 = sv[tid + 3072];
#pragma unroll
        for (int s = 16; s >= 1; s >>= 1) {
            u64 o0 = __shfl_xor_sync(0xffffffffu, r0, s);
            u64 o1 = __shfl_xor_sync(0xffffffffu, r1, s);
            u64 o2 = __shfl_xor_sync(0xffffffffu, r2, s);
            u64 o3 = __shfl_xor_sync(0xffffffffu, r3, s);
            bool m = ((tid & s) == 0);
            r0 = ((r0 < o0) == m) ? r0 : o0;
            r1 = ((r1 < o1) == m) ? r1 : o1;
            r2 = ((r2 < o2) == m) ? r2 : o2;
            r3 = ((r3 < o3) == m) ? r3 : o3;
        }
        g_ckey[base + tid] = r0;
        g_ckey[base + tid + 1024] = r1;
        g_ckey[base + tid + 2048] = r2;
        g_ckey[base + tid + 3072] = r3;
    }
    CLUSTER_SYNC();                        // no CTA exits while peer may read
}

// ---------------- kernel 2c: multi-block gather (sorted rows + boxes) -------
__global__ void __launch_bounds__(256) gather_kernel() {
    int j = blockIdx.x * 256 + threadIdx.x;
    int V = g_V;
    if (j >= V) return;
    int idx = (int)(g_ckey[j] & 0x1FFFu);
    float dd[5];
#pragma unroll
    for (int c = 0; c < 5; c++) {
        dd[c] = g_d[idx * 5 + c];
        g_ds[j * 5 + c] = dd[c];
    }
    g_boxes[j] = make_float4(dd[1] - 0.5f * dd[3], dd[2] - 0.5f * dd[4],
                             dd[1] + 0.5f * dd[3], dd[2] + 0.5f * dd[4]);
}

// ---------------- kernel 3: IoU bitmask (256 rows x 64 cols per block) ------
__global__ void __launch_bounds__(256) mask_kernel() {
    int bx = blockIdx.x;                       // column word 0..127
    int by = blockIdx.y;                       // row tile 0..31 (256 rows each)
    int V = g_V;
    if ((by << 8) >= V || (bx << 6) >= V) return;
    if (bx < (by << 2)) return;                // tile entirely i <= j

    __shared__ float4 cbox[64];
    __shared__ float  carea[64];
    int t = threadIdx.x;
    if (t < 64) {
        int ci = (bx << 6) + t;
        float4 cb = (ci < V) ? g_boxes[ci] : make_float4(0.f, 0.f, 0.f, 0.f);
        cbox[t] = cb;
        carea[t] = fmaxf(cb.z - cb.x, 0.f) * fmaxf(cb.w - cb.y, 0.f);
    }
    __syncthreads();

    int j = (by << 8) + t;
    if (j >= V) return;
    float4 rb = g_boxes[j];
    float  ra = fmaxf(rb.z - rb.x, 0.f) * fmaxf(rb.w - rb.y, 0.f);

    u64 bits = 0ull;
#pragma unroll
    for (int b = 0; b < 64; b++) {
        int i = (bx << 6) + b;
        if (i > j) {
            float iw = fmaxf(fminf(rb.z, cbox[b].z) - fmaxf(rb.x, cbox[b].x), 0.f);
            float ih = fmaxf(fminf(rb.w, cbox[b].w) - fmaxf(rb.y, cbox[b].y), 0.f);
            float inter = iw * ih;
            float uni = ra + carea[b] - inter;
            if (inter > NMS_T * fmaxf(uni, 1e-9f)) bits |= (1ull << b);
        }
    }
    g_mask[(size_t)j * NW + bx] = bits;
}

// ---------------- kernel 4: greedy NMS scan (R8 exact) + fused output -------
__global__ void __launch_bounds__(512) scan_kernel(float* __restrict__ out) {
    __shared__ u64 remv[NW];
    __shared__ u64 skeep[NW];
    __shared__ u64 sdiag[CH][WPC];        // 8KB diagonal block
    __shared__ u64 part[512];
    __shared__ unsigned short klist[CH];
    __shared__ int knum;
    int t = threadIdx.x;
    int V = g_V;
    int NC = (V + CH - 1) / CH;
    int NWv = (V + 63) >> 6;

    if (t == 511) g_cnt = 0;              // deterministic reset for next replay
    if (t < NW) { remv[t] = 0ull; skeep[t] = 0ull; }
    part[t] = 0ull;

    // prefetch diag block of chunk 0 (row = i>>2, word = i&3)
    u64 d0 = 0ull, d1 = 0ull;
    if (NC > 0) {
        d0 = g_mask[(size_t)(t >> 2) * NW + (t & 3)];
        d1 = g_mask[(size_t)((t + 512) >> 2) * NW + ((t + 512) & 3)];
    }
    __syncthreads();

    for (int c = 0; c < NC; c++) {
        sdiag[t >> 2][t & 3] = d0;
        sdiag[(t + 512) >> 2][(t + 512) & 3] = d1;
        // fold prev chunk's propagation partials into remv (word c*WPC + t)
        if (t < NW) {
            int w = c * WPC + t;
            if (w < NW)
                remv[w] |= (part[t * 4] | part[t * 4 + 1]) |
                           (part[t * 4 + 2] | part[t * 4 + 3]);
        }
        __syncthreads();

        // prefetch next chunk's diag block
        if (c + 1 < NC) {
            int base = (c + 1) * CH;
            d0 = g_mask[(size_t)(base + (t >> 2)) * NW + ((c + 1) * WPC + (t & 3))];
            d1 = g_mask[(size_t)(base + ((t + 512) >> 2)) * NW +
                        ((c + 1) * WPC + ((t + 512) & 3))];
        }

        if (t == 0) {
            // simple greedy: EXACT R4/R8 loop (spill-sensitive, do not touch)
            u64 alive[WPC], kept[WPC];
#pragma unroll
            for (int u = 0; u < WPC; u++) {
                int rb = V - ((c * WPC + u) << 6);
                u64 vm = (rb >= 64) ? ~0ull : (rb <= 0 ? 0ull : ((1ull << rb) - 1ull));
                alive[u] = ~remv[c * WPC + u] & vm;
                kept[u] = 0ull;
            }
            int n = 0;
            for (int w = 0; w < WPC; w++) {
                while (alive[w]) {
                    int b = __ffsll((long long)alive[w]) - 1;
                    int rr = (w << 6) + b;
                    kept[w] |= 1ull << b;
                    klist[n++] = (unsigned short)rr;
                    alive[w] &= ~(1ull << b);
                    for (int u = w; u < WPC; u++)
                        alive[u] &= ~sdiag[rr][u];
                }
            }
#pragma unroll
            for (int u = 0; u < WPC; u++) skeep[c * WPC + u] = kept[u];
            knum = n;
        }
        __syncthreads();

        // propagation: 4 threads per word, 4 accumulators (MLP 16/word)
        {
            int w = (c + 1) * WPC + (t >> 2);
            int sub = t & 3;
            u64 a0 = 0ull, a1 = 0ull, a2 = 0ull, a3 = 0ull;
            if (w < NWv) {
                const u64* bp = g_mask + (size_t)(c * CH) * NW + w;
                int n = knum;
                int i = sub;
                for (; i + 12 < n; i += 16) {
                    a0 |= bp[(size_t)klist[i] * NW];
                    a1 |= bp[(size_t)klist[i + 4] * NW];
                    a2 |= bp[(size_t)klist[i + 8] * NW];
                    a3 |= bp[(size_t)klist[i + 12] * NW];
                }
                for (; i < n; i += 4) a0 |= bp[(size_t)klist[i] * NW];
            }
            part[t] = (a0 | a1) | (a2 | a3);
        }
        __syncthreads();
    }

    // fused masked output
    for (int j = t; j < M; j += 512) {
        if (j < V) {
            float f = ((skeep[j >> 6] >> (j & 63)) & 1ull) ? 1.0f : 0.0f;
#pragma unroll
            for (int c5 = 0; c5 < 5; c5++)
                out[j * 5 + c5] = g_ds[j * 5 + c5] * f;
        } else {
#pragma unroll
            for (int c5 = 0; c5 < 5; c5++)
                out[j * 5 + c5] = 0.0f;
        }
    }
}

// ---------------- launcher ---------------------------------------------------
extern "C" void kernel_launch(void* const* d_in, const int* in_sizes, int n_in,
                              void* d_out, int out_size) {
    const float* det = (const float*)d_in[0];
    const float* off = (const float*)d_in[1];
    const float* scl = (const float*)d_in[2];
    const float* bnd = (const float*)d_in[3];
    float* out = (float*)d_out;

    prep_kernel<<<32, 256>>>(det, off, scl, bnd);
    lsort_kernel<<<NTILE, 1024>>>();
    ksort_kernel<<<2, 1024>>>();
    gather_kernel<<<32, 256>>>();
    mask_kernel<<<dim3(NW, 32), 256>>>();
    scan_kernel<<<1, 512>>>(out);
}